// round 10
// baseline (speedup 1.0000x reference)
#include <cuda_runtime.h>
#include <cuda_bf16.h>
#include <cstdint>

// ============================================================================
// TTAggregator via mma.sync.m16n8k16 bf16 (base-ISA HMMA; ptxas targets sm_103
// so tcgen05 is unavailable).
//
// Per step d: ris_new[n,c] = sum_{a,b} U_d[a,b,c]*ris[n,a]*h_d[n,b]
//   k = a*16+b (K=256, 16 k-tiles; k-tile kt <=> a = kt)
//   A (16x16 per kt, row-major) : A[c][b] = U_d[kt][b][c]      (shared!)
//   B (16x8  per kt, col-major) : B[b][n] = ris[n][kt]*h[n][b] (per-row)
// Split precision (fp32 = hi + lo, hi = top-16-bit truncation, exact in bf16):
//   D = Uhi*Zhi + Ulo*Zhi + Uhi*Zlo   (3 contributions; lo*lo ~2^-17 dropped)
// R6: single kt-sweep issuing all 3 contributions per kt into 6 independent
// accumulator chains (pass x even/odd kt) -> HMMA RAW latency fully hidden.
// ============================================================================

static constexpr int NROWS  = 1000000;
static constexpr int DEG    = 10;
static constexpr int TPB    = 256;          // 8 warps
static constexpr int NTILES = 4;            // 8-row tiles per warp -> 32 rows/warp
static constexpr int ROWS_PER_CTA = TPB;    // 256

static constexpr int RIS_STRIDE = 20;       // floats/row: conflict-free + 16B aligned

// smem layout (bytes):
//   ufrag: [d(9)][pass(2)][kt(16)][lane(32)] x uint4  = 147456
//   sris : 256 rows x 20 f32                          =  20480
//   sUo, sU0 : 1KB each
static constexpr int SM_UFRAG = 0;
static constexpr int SM_RIS   = 9 * 2 * 16 * 512;            // 147456
static constexpr int SM_UO    = SM_RIS + ROWS_PER_CTA * RIS_STRIDE * 4;
static constexpr int SM_U0    = SM_UO + 1024;
static constexpr int SMEM_BYTES = SM_U0 + 1024;              // 169984

// ---- packing helpers ----
__device__ __forceinline__ uint32_t pack_hi(float x, float y) {
    uint32_t r;
    asm("prmt.b32 %0, %1, %2, 0x7632;"
        : "=r"(r) : "r"(__float_as_uint(x)), "r"(__float_as_uint(y)));
    return r;
}
__device__ __forceinline__ uint32_t pack_lo(float x, float y, uint32_t hibits) {
    float hx = __uint_as_float(hibits << 16);
    float hy = __uint_as_float(hibits & 0xffff0000u);
    float lx = x - hx;          // exact (Dekker-style split)
    float ly = y - hy;
    uint32_t r;
    asm("cvt.rn.bf16x2.f32 %0, %1, %2;" : "=r"(r) : "f"(ly), "f"(lx));
    return r;
}
__device__ __forceinline__ uint32_t pack_lo_direct(float x, float y) {
    float hx = __uint_as_float(__float_as_uint(x) & 0xffff0000u);
    float hy = __uint_as_float(__float_as_uint(y) & 0xffff0000u);
    float lx = x - hx, ly = y - hy;
    uint32_t r;
    asm("cvt.rn.bf16x2.f32 %0, %1, %2;" : "=r"(r) : "f"(ly), "f"(lx));
    return r;
}

struct F4 { float x, y, z, w; };

__device__ __forceinline__ void mma16816(F4& d, const uint4& a, uint32_t b0, uint32_t b1) {
    asm volatile(
        "mma.sync.aligned.m16n8k16.row.col.f32.bf16.bf16.f32 "
        "{%0,%1,%2,%3}, {%4,%5,%6,%7}, {%8,%9}, {%0,%1,%2,%3};"
        : "+f"(d.x), "+f"(d.y), "+f"(d.z), "+f"(d.w)
        : "r"(a.x), "r"(a.y), "r"(a.z), "r"(a.w), "r"(b0), "r"(b1));
}

__global__ __launch_bounds__(TPB, 1)
void tt_mma_kernel(const float* __restrict__ ns,
                   const float* __restrict__ U0,
                   const float* __restrict__ Ur,
                   const float* __restrict__ Uo,
                   float* __restrict__ out)
{
    extern __shared__ char smem[];
    uint32_t* ufrag = (uint32_t*)(smem + SM_UFRAG);
    float*    sris  = (float*)(smem + SM_RIS);
    float*    sUo   = (float*)(smem + SM_UO);
    float*    sU0   = (float*)(smem + SM_U0);

    const int tid  = threadIdx.x;
    const int lane = tid & 31;
    const int w    = tid >> 5;
    const int m    = lane & 3;      // threadID_in_group
    const int g    = lane >> 2;     // groupID
    const long long cta_row0 = (long long)blockIdx.x * ROWS_PER_CTA;

    // ---- build U hi/lo A-fragments in exact mma fragment order ----
    for (int i = tid; i < 9 * 16 * 32; i += TPB) {
        int d  = i >> 9;
        int kt = (i >> 5) & 15;
        int ln = i & 31;
        int lm = ln & 3, lg = ln >> 2;
        const float* Ua = Ur + d * 4096 + kt * 256;   // [b][c]
        float u00 = Ua[(2*lm    )*16 + lg    ], u01 = Ua[(2*lm + 1)*16 + lg    ];
        float u10 = Ua[(2*lm    )*16 + lg + 8], u11 = Ua[(2*lm + 1)*16 + lg + 8];
        float u20 = Ua[(2*lm + 8)*16 + lg    ], u21 = Ua[(2*lm + 9)*16 + lg    ];
        float u30 = Ua[(2*lm + 8)*16 + lg + 8], u31 = Ua[(2*lm + 9)*16 + lg + 8];
        uint4 hi = make_uint4(pack_hi(u00,u01), pack_hi(u10,u11),
                              pack_hi(u20,u21), pack_hi(u30,u31));
        uint4 lo = make_uint4(pack_lo_direct(u00,u01), pack_lo_direct(u10,u11),
                              pack_lo_direct(u20,u21), pack_lo_direct(u30,u31));
        *(uint4*)&ufrag[((d*2 + 0)*16 + kt)*128 + ln*4] = hi;
        *(uint4*)&ufrag[((d*2 + 1)*16 + kt)*128 + ln*4] = lo;
    }
    for (int i = tid; i < 256; i += TPB) { sU0[i] = U0[i]; sUo[i] = Uo[i]; }
    __syncthreads();

    // ---- ris0 = U0^T h0, one thread per row ----
    {
        long long r = cta_row0 + tid; if (r > NROWS - 1) r = NROWS - 1;
        const float* p = ns + (size_t)r * (DEG * 16);
        float h0[16];
        #pragma unroll
        for (int q = 0; q < 4; q++) {
            float4 v = *(const float4*)(p + q * 4);
            h0[4*q] = v.x; h0[4*q+1] = v.y; h0[4*q+2] = v.z; h0[4*q+3] = v.w;
        }
        float acc[16];
        #pragma unroll
        for (int c = 0; c < 16; c++) acc[c] = 0.f;
        #pragma unroll
        for (int b = 0; b < 16; b++) {
            float hb = h0[b];
            #pragma unroll
            for (int c = 0; c < 16; c++) acc[c] = fmaf(sU0[b*16 + c], hb, acc[c]);
        }
        #pragma unroll
        for (int c = 0; c < 16; c++) sris[tid * RIS_STRIDE + c] = acc[c];
    }
    __syncwarp();

    // ================= main loop: 9 TT steps, warps independent =============
    #pragma unroll 1
    for (int d = 1; d < DEG; d++) {
        // U fragments resident in registers for the whole step
        const uint32_t* fh = &ufrag[((d-1)*2 + 0) * 2048];
        const uint32_t* fl = &ufrag[((d-1)*2 + 1) * 2048];
        uint4 uh[16], ul[16];
        #pragma unroll
        for (int kt = 0; kt < 16; kt++) {
            uh[kt] = *(const uint4*)&fh[kt*128 + lane*4];
            ul[kt] = *(const uint4*)&fl[kt*128 + lane*4];
        }
        // prefetch this step's h values for all 4 tiles (MLP=8)
        float2 ha[NTILES], hb[NTILES];
        #pragma unroll
        for (int T = 0; T < NTILES; T++) {
            long long r = cta_row0 + w*32 + T*8 + g; if (r > NROWS - 1) r = NROWS - 1;
            const float* p = ns + (size_t)r * (DEG * 16) + d * 16 + 2 * m;
            ha[T] = *(const float2*)p;
            hb[T] = *(const float2*)(p + 8);
        }

        #pragma unroll 1
        for (int T = 0; T < NTILES; T++) {
            const int rowbase = w*32 + T*8;
            // my row's ris (row index n = g within the tile)
            const float4* rp = (const float4*)&sris[(rowbase + g) * RIS_STRIDE];
            float4 q0 = rp[0], q1 = rp[1], q2 = rp[2], q3 = rp[3];
            float r16[16] = { q0.x,q0.y,q0.z,q0.w, q1.x,q1.y,q1.z,q1.w,
                              q2.x,q2.y,q2.z,q2.w, q3.x,q3.y,q3.z,q3.w };
            __syncwarp();   // all lanes read old ris before anyone overwrites

            // 6 independent accumulator chains: pass{UhiZhi,UloZhi,UhiZlo} x {even,odd kt}
            F4 acc[6];
            #pragma unroll
            for (int i = 0; i < 6; i++) acc[i] = F4{0,0,0,0};

            #pragma unroll
            for (int kt = 0; kt < 16; kt++) {
                const int par = (kt & 1) * 3;
                float z0 = r16[kt]*ha[T].x, z1 = r16[kt]*ha[T].y;
                float z2 = r16[kt]*hb[T].x, z3 = r16[kt]*hb[T].y;
                uint32_t zh0 = pack_hi(z0, z1);
                uint32_t zh1 = pack_hi(z2, z3);
                mma16816(acc[par + 0], uh[kt], zh0, zh1);
                mma16816(acc[par + 1], ul[kt], zh0, zh1);
                uint32_t zl0 = pack_lo(z0, z1, zh0);
                uint32_t zl1 = pack_lo(z2, z3, zh1);
                mma16816(acc[par + 2], uh[kt], zl0, zl1);
            }

            // D frag: lane holds channels {g, g+8} of rows {2m, 2m+1}
            const int r0w = rowbase + 2*m, r1w = r0w + 1;
            sris[r0w*RIS_STRIDE + g    ] = ((acc[0].x + acc[3].x) + (acc[1].x + acc[4].x)) + (acc[2].x + acc[5].x);
            sris[r1w*RIS_STRIDE + g    ] = ((acc[0].y + acc[3].y) + (acc[1].y + acc[4].y)) + (acc[2].y + acc[5].y);
            sris[r0w*RIS_STRIDE + g + 8] = ((acc[0].z + acc[3].z) + (acc[1].z + acc[4].z)) + (acc[2].z + acc[5].z);
            sris[r1w*RIS_STRIDE + g + 8] = ((acc[0].w + acc[3].w) + (acc[1].w + acc[4].w)) + (acc[2].w + acc[5].w);
            __syncwarp();
        }
    }

    // ---- output projection: out[c] = sum_a Uo[a,c] * ris[a] ----
    const long long orow = cta_row0 + tid;
    if (orow < NROWS) {
        const float4* rp = (const float4*)&sris[tid * RIS_STRIDE];
        float4 q0 = rp[0], q1 = rp[1], q2 = rp[2], q3 = rp[3];
        float rv[16] = { q0.x,q0.y,q0.z,q0.w, q1.x,q1.y,q1.z,q1.w,
                         q2.x,q2.y,q2.z,q2.w, q3.x,q3.y,q3.z,q3.w };
        float o[16];
        #pragma unroll
        for (int c = 0; c < 16; c++) o[c] = 0.f;
        #pragma unroll
        for (int a = 0; a < 16; a++) {
            float ra = rv[a];
            #pragma unroll
            for (int c = 0; c < 16; c++) o[c] = fmaf(sUo[a*16 + c], ra, o[c]);
        }
        float4* op = (float4*)(out + (size_t)orow * 16);
        #pragma unroll
        for (int q = 0; q < 4; q++)
            op[q] = make_float4(o[4*q], o[4*q+1], o[4*q+2], o[4*q+3]);
    }
}

extern "C" void kernel_launch(void* const* d_in, const int* in_sizes, int n_in,
                              void* d_out, int out_size)
{
    const float* ns = (const float*)d_in[0];
    const float* U0 = (const float*)d_in[1];
    const float* Ur = (const float*)d_in[2];
    const float* Uo = (const float*)d_in[3];
    float* out = (float*)d_out;

    cudaFuncSetAttribute(tt_mma_kernel,
                         cudaFuncAttributeMaxDynamicSharedMemorySize, SMEM_BYTES);

    int grid = (NROWS + ROWS_PER_CTA - 1) / ROWS_PER_CTA;
    tt_mma_kernel<<<grid, TPB, SMEM_BYTES>>>(ns, U0, Ur, Uo, out);
}

// round 12
// speedup vs baseline: 1.1742x; 1.1742x over previous
#include <cuda_runtime.h>
#include <cuda_bf16.h>
#include <cstdint>

// ============================================================================
// TTAggregator via mma.sync.m16n8k16 bf16 (base-ISA HMMA; ptxas targets sm_103
// so tcgen05 is unavailable).
//
// Per step d: ris_new[n,c] = sum_{a,b} U_d[a,b,c]*ris[n,a]*h_d[n,b]
//   k = a*16+b (K=256, 16 k-tiles; kt <=> a)
//   A (16x16 per kt, row-major) : A[c][b] = U_d[kt][b][c]      (shared!)
//   B (16x8  per kt, col-major) : B[b][n] = ris[n][kt]*h[n][b] (per-row)
// Split precision (fp32 = hi + lo, hi = top-16-bit truncation, exact in bf16):
//   D = Uhi*Zhi + Ulo*Zhi + Uhi*Zlo   (3 contributions; lo*lo ~2^-17 dropped)
//
// R12 = R11 (TPB=512, U streamed from smem, 16 warps/SM) + the missing
// __syncthreads() before the output projection: with 16 rows/warp the output
// stage reads rows written by a DIFFERENT warp, so warp-level sync is not
// enough (this was the R11 correctness failure).
// ============================================================================

static constexpr int NROWS  = 1000000;
static constexpr int DEG    = 10;
static constexpr int TPB    = 512;           // 16 warps
static constexpr int NT     = 2;             // 8-row tiles per warp -> 16 rows/warp
static constexpr int ROWS_PER_CTA = 16 * 16; // 256

static constexpr int RIS_STRIDE = 20;        // floats/row: conflict-free + 16B aligned

// smem layout (bytes):
//   ufrag: [d(9)][pass(2)][kt(16)][lane(32)] x uint4  = 147456
//   sris : 256 rows x 20 f32                          =  20480
//   sUo, sU0 : 1KB each
static constexpr int SM_UFRAG = 0;
static constexpr int SM_RIS   = 9 * 2 * 16 * 512;            // 147456
static constexpr int SM_UO    = SM_RIS + ROWS_PER_CTA * RIS_STRIDE * 4;
static constexpr int SM_U0    = SM_UO + 1024;
static constexpr int SMEM_BYTES = SM_U0 + 1024;              // 169984

// ---- packing helpers ----
__device__ __forceinline__ uint32_t pack_hi(float x, float y) {
    uint32_t r;
    asm("prmt.b32 %0, %1, %2, 0x7632;"
        : "=r"(r) : "r"(__float_as_uint(x)), "r"(__float_as_uint(y)));
    return r;
}
__device__ __forceinline__ uint32_t pack_lo(float x, float y, uint32_t hibits) {
    float hx = __uint_as_float(hibits << 16);
    float hy = __uint_as_float(hibits & 0xffff0000u);
    float lx = x - hx;          // exact (Dekker-style split)
    float ly = y - hy;
    uint32_t r;
    asm("cvt.rn.bf16x2.f32 %0, %1, %2;" : "=r"(r) : "f"(ly), "f"(lx));
    return r;
}
__device__ __forceinline__ uint32_t pack_lo_direct(float x, float y) {
    float hx = __uint_as_float(__float_as_uint(x) & 0xffff0000u);
    float hy = __uint_as_float(__float_as_uint(y) & 0xffff0000u);
    float lx = x - hx, ly = y - hy;
    uint32_t r;
    asm("cvt.rn.bf16x2.f32 %0, %1, %2;" : "=r"(r) : "f"(ly), "f"(lx));
    return r;
}

// ---- packed f32x2 ----
__device__ __forceinline__ unsigned long long f2_pack(float x, float y) {
    unsigned long long r;
    asm("mov.b64 %0, {%1, %2};" : "=l"(r) : "f"(x), "f"(y));
    return r;
}
__device__ __forceinline__ unsigned long long f2_mul(unsigned long long a, unsigned long long b) {
    unsigned long long d;
    asm("mul.rn.f32x2 %0, %1, %2;" : "=l"(d) : "l"(a), "l"(b));
    return d;
}
__device__ __forceinline__ void f2_unpack(unsigned long long v, float& x, float& y) {
    asm("mov.b64 {%0, %1}, %2;" : "=f"(x), "=f"(y) : "l"(v));
}

struct F4 { float x, y, z, w; };

__device__ __forceinline__ void mma16816(F4& d, const uint4& a, uint32_t b0, uint32_t b1) {
    asm volatile(
        "mma.sync.aligned.m16n8k16.row.col.f32.bf16.bf16.f32 "
        "{%0,%1,%2,%3}, {%4,%5,%6,%7}, {%8,%9}, {%0,%1,%2,%3};"
        : "+f"(d.x), "+f"(d.y), "+f"(d.z), "+f"(d.w)
        : "r"(a.x), "r"(a.y), "r"(a.z), "r"(a.w), "r"(b0), "r"(b1));
}

__global__ __launch_bounds__(TPB, 1)
void tt_mma_kernel(const float* __restrict__ ns,
                   const float* __restrict__ U0,
                   const float* __restrict__ Ur,
                   const float* __restrict__ Uo,
                   float* __restrict__ out)
{
    extern __shared__ char smem[];
    uint32_t* ufrag = (uint32_t*)(smem + SM_UFRAG);
    float*    sris  = (float*)(smem + SM_RIS);
    float*    sUo   = (float*)(smem + SM_UO);
    float*    sU0   = (float*)(smem + SM_U0);

    const int tid  = threadIdx.x;
    const int lane = tid & 31;
    const int w    = tid >> 5;
    const int m    = lane & 3;      // threadID_in_group
    const int g    = lane >> 2;     // groupID
    const long long cta_row0 = (long long)blockIdx.x * ROWS_PER_CTA;

    // ---- build U hi/lo A-fragments in exact mma fragment order ----
    for (int i = tid; i < 9 * 16 * 32; i += TPB) {
        int d  = i >> 9;
        int kt = (i >> 5) & 15;
        int ln = i & 31;
        int lm = ln & 3, lg = ln >> 2;
        const float* Ua = Ur + d * 4096 + kt * 256;   // [b][c]
        float u00 = Ua[(2*lm    )*16 + lg    ], u01 = Ua[(2*lm + 1)*16 + lg    ];
        float u10 = Ua[(2*lm    )*16 + lg + 8], u11 = Ua[(2*lm + 1)*16 + lg + 8];
        float u20 = Ua[(2*lm + 8)*16 + lg    ], u21 = Ua[(2*lm + 9)*16 + lg    ];
        float u30 = Ua[(2*lm + 8)*16 + lg + 8], u31 = Ua[(2*lm + 9)*16 + lg + 8];
        uint4 hi = make_uint4(pack_hi(u00,u01), pack_hi(u10,u11),
                              pack_hi(u20,u21), pack_hi(u30,u31));
        uint4 lo = make_uint4(pack_lo_direct(u00,u01), pack_lo_direct(u10,u11),
                              pack_lo_direct(u20,u21), pack_lo_direct(u30,u31));
        *(uint4*)&ufrag[((d*2 + 0)*16 + kt)*128 + ln*4] = hi;
        *(uint4*)&ufrag[((d*2 + 1)*16 + kt)*128 + ln*4] = lo;
    }
    for (int i = tid; i < 256; i += TPB) { sU0[i] = U0[i]; sUo[i] = Uo[i]; }
    __syncthreads();

    // ---- ris0 = U0^T h0, one thread per row (first 256 threads) ----
    if (tid < ROWS_PER_CTA) {
        long long r = cta_row0 + tid; if (r > NROWS - 1) r = NROWS - 1;
        const float* p = ns + (size_t)r * (DEG * 16);
        float h0[16];
        #pragma unroll
        for (int q = 0; q < 4; q++) {
            float4 v = *(const float4*)(p + q * 4);
            h0[4*q] = v.x; h0[4*q+1] = v.y; h0[4*q+2] = v.z; h0[4*q+3] = v.w;
        }
        float acc[16];
        #pragma unroll
        for (int c = 0; c < 16; c++) acc[c] = 0.f;
        #pragma unroll
        for (int b = 0; b < 16; b++) {
            float hb = h0[b];
            #pragma unroll
            for (int c = 0; c < 16; c++) acc[c] = fmaf(sU0[b*16 + c], hb, acc[c]);
        }
        #pragma unroll
        for (int c = 0; c < 16; c++) sris[tid * RIS_STRIDE + c] = acc[c];
    }
    __syncthreads();

    const int rowbase = w * 16;     // this warp's 16 rows (warp-exclusive in main loop)

    // ================= main loop: 9 TT steps, warps independent =============
    #pragma unroll 1
    for (int d = 1; d < DEG; d++) {
        const uint32_t* fh = &ufrag[((d-1)*2 + 0) * 2048];
        const uint32_t* fl = &ufrag[((d-1)*2 + 1) * 2048];

        // h values for both tiles, packed: {h[2m],h[2m+1]}, {h[2m+8],h[2m+9]}
        unsigned long long hha[NT], hhb[NT];
        #pragma unroll
        for (int T = 0; T < NT; T++) {
            long long r = cta_row0 + rowbase + T*8 + g; if (r > NROWS - 1) r = NROWS - 1;
            const float* p = ns + (size_t)r * (DEG * 16) + d * 16 + 2 * m;
            float2 va = *(const float2*)p;
            float2 vb = *(const float2*)(p + 8);
            hha[T] = f2_pack(va.x, va.y);
            hhb[T] = f2_pack(vb.x, vb.y);
        }

        // my rows' ris (lane's row = g within each tile)
        float r16[NT][16];
        #pragma unroll
        for (int T = 0; T < NT; T++) {
            const float4* rp = (const float4*)&sris[(rowbase + T*8 + g) * RIS_STRIDE];
            float4 q0 = rp[0], q1 = rp[1], q2 = rp[2], q3 = rp[3];
            r16[T][0]=q0.x;  r16[T][1]=q0.y;  r16[T][2]=q0.z;  r16[T][3]=q0.w;
            r16[T][4]=q1.x;  r16[T][5]=q1.y;  r16[T][6]=q1.z;  r16[T][7]=q1.w;
            r16[T][8]=q2.x;  r16[T][9]=q2.y;  r16[T][10]=q2.z; r16[T][11]=q2.w;
            r16[T][12]=q3.x; r16[T][13]=q3.y; r16[T][14]=q3.z; r16[T][15]=q3.w;
        }
        __syncwarp();   // all lanes read old ris before anyone overwrites

        // 3 chains per tile (UhiZhi, UloZhi, UhiZlo); same chain touched every
        // 6 MMAs -> RAW spacing comfortably exceeds HMMA latency
        F4 acc[NT][3];
        #pragma unroll
        for (int T = 0; T < NT; T++)
            #pragma unroll
            for (int p = 0; p < 3; p++) acc[T][p] = F4{0,0,0,0};

        #pragma unroll
        for (int kt = 0; kt < 16; kt++) {
            // stream this kt's U fragments from smem (conflict-free LDS.128)
            uint4 uh = *(const uint4*)&fh[kt*128 + lane*4];
            uint4 ul = *(const uint4*)&fl[kt*128 + lane*4];
            #pragma unroll
            for (int T = 0; T < NT; T++) {
                unsigned long long rr = f2_pack(r16[T][kt], r16[T][kt]);
                unsigned long long za = f2_mul(rr, hha[T]);
                unsigned long long zb = f2_mul(rr, hhb[T]);
                float z0, z1, z2, z3;
                f2_unpack(za, z0, z1);
                f2_unpack(zb, z2, z3);
                uint32_t zh0 = pack_hi(z0, z1);
                uint32_t zh1 = pack_hi(z2, z3);
                mma16816(acc[T][0], uh, zh0, zh1);
                mma16816(acc[T][1], ul, zh0, zh1);
                uint32_t zl0 = pack_lo(z0, z1, zh0);
                uint32_t zl1 = pack_lo(z2, z3, zh1);
                mma16816(acc[T][2], uh, zl0, zl1);
            }
        }

        // D frag: lane holds channels {g, g+8} of rows {2m, 2m+1} per tile
        #pragma unroll
        for (int T = 0; T < NT; T++) {
            const int r0w = rowbase + T*8 + 2*m, r1w = r0w + 1;
            sris[r0w*RIS_STRIDE + g    ] = (acc[T][0].x + acc[T][1].x) + acc[T][2].x;
            sris[r1w*RIS_STRIDE + g    ] = (acc[T][0].y + acc[T][1].y) + acc[T][2].y;
            sris[r0w*RIS_STRIDE + g + 8] = (acc[T][0].z + acc[T][1].z) + acc[T][2].z;
            sris[r1w*RIS_STRIDE + g + 8] = (acc[T][0].w + acc[T][1].w) + acc[T][2].w;
        }
        __syncwarp();
    }

    // Output stage reads rows written by OTHER warps (16 rows/warp vs 32
    // threads/warp) -> must be a CTA-wide barrier. This was the R11 bug.
    __syncthreads();

    // ---- output projection: out[c] = sum_a Uo[a,c] * ris[a] ----
    if (tid < ROWS_PER_CTA) {
        const long long orow = cta_row0 + tid;
        if (orow < NROWS) {
            const float4* rp = (const float4*)&sris[tid * RIS_STRIDE];
            float4 q0 = rp[0], q1 = rp[1], q2 = rp[2], q3 = rp[3];
            float rv[16] = { q0.x,q0.y,q0.z,q0.w, q1.x,q1.y,q1.z,q1.w,
                             q2.x,q2.y,q2.z,q2.w, q3.x,q3.y,q3.z,q3.w };
            float o[16];
            #pragma unroll
            for (int c = 0; c < 16; c++) o[c] = 0.f;
            #pragma unroll
            for (int a = 0; a < 16; a++) {
                float ra = rv[a];
                #pragma unroll
                for (int c = 0; c < 16; c++) o[c] = fmaf(sUo[a*16 + c], ra, o[c]);
            }
            float4* op = (float4*)(out + (size_t)orow * 16);
            #pragma unroll
            for (int q = 0; q < 4; q++)
                op[q] = make_float4(o[4*q], o[4*q+1], o[4*q+2], o[4*q+3]);
        }
    }
}

extern "C" void kernel_launch(void* const* d_in, const int* in_sizes, int n_in,
                              void* d_out, int out_size)
{
    const float* ns = (const float*)d_in[0];
    const float* U0 = (const float*)d_in[1];
    const float* Ur = (const float*)d_in[2];
    const float* Uo = (const float*)d_in[3];
    float* out = (float*)d_out;

    cudaFuncSetAttribute(tt_mma_kernel,
                         cudaFuncAttributeMaxDynamicSharedMemorySize, SMEM_BYTES);

    int grid = (NROWS + ROWS_PER_CTA - 1) / ROWS_PER_CTA;
    tt_mma_kernel<<<grid, TPB, SMEM_BYTES>>>(ns, U0, Ur, Uo, out);
}

// round 13
// speedup vs baseline: 1.4501x; 1.2350x over previous
#include <cuda_runtime.h>
#include <cuda_bf16.h>
#include <cstdint>

// ============================================================================
// TTAggregator via mma.sync.m16n8k16 bf16 (base-ISA HMMA; harness ptxas
// targets sm_103, no tcgen05).
//
// Per step d: ris_new[n,c] = sum_{a,b} U_d[a,b,c]*ris[n,a]*h_d[n,b]
//   k = a*16+b (K=256, 16 k-tiles; kt <=> a)
//   A (16x16 per kt, row-major) : A[c][b] = U_d[kt][b][c]      (shared!)
//   B (16x8  per kt, col-major) : B[b][n] = ris[n][kt]*h[n][b] (per-row)
// Split precision: D = Uhi*Zhi + Ulo*Zhi + Uhi*Zlo (lo*lo ~2^-17 dropped).
//
// R13: occupancy push #2.
//  - U fragments live in a __device__ global table (built by a pre-kernel),
//    read via coalesced LDG.128 + L1 cache -> CTA smem drops 170KB -> 12KB.
//  - ris re-read from smem per kt (broadcast LDS.32) -> 32 fewer regs.
//  - TPB=256, __launch_bounds__(256,3) -> 3 CTAs/SM = 24 warps (6/SMSP).
// Tensor roofline (HMMA.16816 ~ 1/2cyc/SM, 54.2M HMMAs) ~ 405-450 us.
// ============================================================================

static constexpr int NROWS  = 1000000;
static constexpr int DEG    = 10;
static constexpr int TPB    = 256;           // 8 warps
static constexpr int NT     = 2;             // 2 8-row tiles/warp -> 16 rows/warp
static constexpr int ROWS_PER_CTA = 8 * 16;  // 128

static constexpr int RIS_STRIDE = 20;        // floats/row: conflict-free + 16B aligned

// smem (floats): sris 128*20, then U0 256, Uo 256
static constexpr int SM_RIS_F = 0;
static constexpr int SM_U0_F  = ROWS_PER_CTA * RIS_STRIDE;       // 2560
static constexpr int SM_UO_F  = SM_U0_F + 256;
static constexpr int SMEM_BYTES = (SM_UO_F + 256) * 4;           // 12288

// U fragment table: [d(9)][pass(2)][kt(16)][lane(32)] uint4
__device__ uint4 g_ufrag[9 * 2 * 16 * 32];

// ---- packing helpers ----
__device__ __forceinline__ uint32_t pack_hi(float x, float y) {
    uint32_t r;
    asm("prmt.b32 %0, %1, %2, 0x7632;"
        : "=r"(r) : "r"(__float_as_uint(x)), "r"(__float_as_uint(y)));
    return r;
}
__device__ __forceinline__ uint32_t pack_lo_direct(float x, float y) {
    float hx = __uint_as_float(__float_as_uint(x) & 0xffff0000u);
    float hy = __uint_as_float(__float_as_uint(y) & 0xffff0000u);
    float lx = x - hx, ly = y - hy;
    uint32_t r;
    asm("cvt.rn.bf16x2.f32 %0, %1, %2;" : "=r"(r) : "f"(ly), "f"(lx));
    return r;
}

// ---- packed f32x2 ----
__device__ __forceinline__ unsigned long long f2_pack(float x, float y) {
    unsigned long long r;
    asm("mov.b64 %0, {%1, %2};" : "=l"(r) : "f"(x), "f"(y));
    return r;
}
__device__ __forceinline__ unsigned long long f2_mul(unsigned long long a, unsigned long long b) {
    unsigned long long d;
    asm("mul.rn.f32x2 %0, %1, %2;" : "=l"(d) : "l"(a), "l"(b));
    return d;
}
__device__ __forceinline__ unsigned long long f2_fma(unsigned long long a, unsigned long long b,
                                                     unsigned long long c) {
    unsigned long long d;
    asm("fma.rn.f32x2 %0, %1, %2, %3;" : "=l"(d) : "l"(a), "l"(b), "l"(c));
    return d;
}
__device__ __forceinline__ void f2_unpack(unsigned long long v, float& x, float& y) {
    asm("mov.b64 {%0, %1}, %2;" : "=f"(x), "=f"(y) : "l"(v));
}

struct F4 { float x, y, z, w; };

__device__ __forceinline__ void mma16816(F4& d, const uint4& a, uint32_t b0, uint32_t b1) {
    asm volatile(
        "mma.sync.aligned.m16n8k16.row.col.f32.bf16.bf16.f32 "
        "{%0,%1,%2,%3}, {%4,%5,%6,%7}, {%8,%9}, {%0,%1,%2,%3};"
        : "+f"(d.x), "+f"(d.y), "+f"(d.z), "+f"(d.w)
        : "r"(a.x), "r"(a.y), "r"(a.z), "r"(a.w), "r"(b0), "r"(b1));
}

// ---- pre-kernel: build U hi/lo A-fragments in mma fragment order ----
__global__ void build_ufrag_kernel(const float* __restrict__ Ur)
{
    int i = blockIdx.x * blockDim.x + threadIdx.x;   // 0 .. 9*16*32-1
    if (i >= 9 * 16 * 32) return;
    int d  = i >> 9;
    int kt = (i >> 5) & 15;
    int ln = i & 31;
    int lm = ln & 3, lg = ln >> 2;
    const float* Ua = Ur + d * 4096 + kt * 256;      // [b][c]
    float u00 = Ua[(2*lm    )*16 + lg    ], u01 = Ua[(2*lm + 1)*16 + lg    ];
    float u10 = Ua[(2*lm    )*16 + lg + 8], u11 = Ua[(2*lm + 1)*16 + lg + 8];
    float u20 = Ua[(2*lm + 8)*16 + lg    ], u21 = Ua[(2*lm + 9)*16 + lg    ];
    float u30 = Ua[(2*lm + 8)*16 + lg + 8], u31 = Ua[(2*lm + 9)*16 + lg + 8];
    uint4 hi = make_uint4(pack_hi(u00,u01), pack_hi(u10,u11),
                          pack_hi(u20,u21), pack_hi(u30,u31));
    uint4 lo = make_uint4(pack_lo_direct(u00,u01), pack_lo_direct(u10,u11),
                          pack_lo_direct(u20,u21), pack_lo_direct(u30,u31));
    g_ufrag[((d*2 + 0)*16 + kt)*32 + ln] = hi;
    g_ufrag[((d*2 + 1)*16 + kt)*32 + ln] = lo;
}

__global__ __launch_bounds__(TPB, 3)
void tt_mma_kernel(const float* __restrict__ ns,
                   const float* __restrict__ U0,
                   const float* __restrict__ Uo,
                   float* __restrict__ out)
{
    extern __shared__ float smf[];
    float* sris = smf + SM_RIS_F;
    float* sU0  = smf + SM_U0_F;
    float* sUo  = smf + SM_UO_F;

    const int tid  = threadIdx.x;
    const int lane = tid & 31;
    const int w    = tid >> 5;
    const int m    = lane & 3;      // threadID_in_group
    const int g    = lane >> 2;     // groupID
    const long long cta_row0 = (long long)blockIdx.x * ROWS_PER_CTA;

    for (int i = tid; i < 256; i += TPB) { sU0[i] = U0[i]; sUo[i] = Uo[i]; }
    __syncthreads();

    // ---- ris0 = U0^T h0, one thread per row (first 128 threads) ----
    if (tid < ROWS_PER_CTA) {
        long long r = cta_row0 + tid; if (r > NROWS - 1) r = NROWS - 1;
        const float* p = ns + (size_t)r * (DEG * 16);
        float h0[16];
        #pragma unroll
        for (int q = 0; q < 4; q++) {
            float4 v = *(const float4*)(p + q * 4);
            h0[4*q] = v.x; h0[4*q+1] = v.y; h0[4*q+2] = v.z; h0[4*q+3] = v.w;
        }
        float acc[16];
        #pragma unroll
        for (int c = 0; c < 16; c++) acc[c] = 0.f;
        #pragma unroll
        for (int b = 0; b < 16; b++) {
            float hb = h0[b];
            #pragma unroll
            for (int c = 0; c < 16; c++) acc[c] = fmaf(sU0[b*16 + c], hb, acc[c]);
        }
        #pragma unroll
        for (int c = 0; c < 16; c++) sris[tid * RIS_STRIDE + c] = acc[c];
    }
    __syncthreads();

    const int rowbase = w * 16;     // warp-exclusive 16 rows in main loop

    const unsigned long long NEG1   = f2_pack(-1.0f, -1.0f);
    const unsigned long long MASK64 = 0xffff0000ffff0000ull;

    // ================= main loop: 9 TT steps, warps independent =============
    #pragma unroll 1
    for (int d = 1; d < DEG; d++) {
        const uint4* fh = g_ufrag + ((d-1)*2 + 0) * 512;
        const uint4* fl = g_ufrag + ((d-1)*2 + 1) * 512;

        // h values for both tiles: {h[2m],h[2m+1]}, {h[2m+8],h[2m+9]}
        unsigned long long hha[NT], hhb[NT];
        #pragma unroll
        for (int T = 0; T < NT; T++) {
            long long r = cta_row0 + rowbase + T*8 + g; if (r > NROWS - 1) r = NROWS - 1;
            const float* p = ns + (size_t)r * (DEG * 16) + d * 16 + 2 * m;
            float2 va = *(const float2*)p;
            float2 vb = *(const float2*)(p + 8);
            hha[T] = f2_pack(va.x, va.y);
            hhb[T] = f2_pack(vb.x, vb.y);
        }

        // ris rows re-read from smem per kt (broadcast LDS.32, bank-clean)
        const float* rp0 = &sris[(rowbase + 0*8 + g) * RIS_STRIDE];
        const float* rp1 = &sris[(rowbase + 1*8 + g) * RIS_STRIDE];

        // 3 chains per tile (UhiZhi, UloZhi, UhiZlo)
        F4 acc[NT][3];
        #pragma unroll
        for (int T = 0; T < NT; T++)
            #pragma unroll
            for (int p = 0; p < 3; p++) acc[T][p] = F4{0,0,0,0};

        #pragma unroll
        for (int kt = 0; kt < 16; kt++) {
            // stream this kt's U fragments (coalesced 512B LDG.128, L1-hot)
            uint4 uh = __ldg(&fh[kt*32 + lane]);
            uint4 ul = __ldg(&fl[kt*32 + lane]);
            float ra[NT] = { rp0[kt], rp1[kt] };
            #pragma unroll
            for (int T = 0; T < NT; T++) {
                unsigned long long rr = f2_pack(ra[T], ra[T]);
                unsigned long long za = f2_mul(rr, hha[T]);
                unsigned long long zb = f2_mul(rr, hhb[T]);
                float z0, z1, z2, z3;
                f2_unpack(za, z0, z1);
                f2_unpack(zb, z2, z3);
                uint32_t zh0 = pack_hi(z0, z1);
                uint32_t zh1 = pack_hi(z2, z3);
                mma16816(acc[T][0], uh, zh0, zh1);
                mma16816(acc[T][1], ul, zh0, zh1);
                // lo residuals: exact z - trunc(z) via masked fma (f32x2)
                unsigned long long la = f2_fma(za & MASK64, NEG1, za);
                unsigned long long lb = f2_fma(zb & MASK64, NEG1, zb);
                float l0, l1, l2, l3;
                f2_unpack(la, l0, l1);
                f2_unpack(lb, l2, l3);
                uint32_t zl0, zl1;
                asm("cvt.rn.bf16x2.f32 %0, %1, %2;" : "=r"(zl0) : "f"(l1), "f"(l0));
                asm("cvt.rn.bf16x2.f32 %0, %1, %2;" : "=r"(zl1) : "f"(l3), "f"(l2));
                mma16816(acc[T][2], uh, zl0, zl1);
            }
        }
        __syncwarp();   // all lanes done reading old ris before overwrite

        // D frag: lane holds channels {g, g+8} of rows {2m, 2m+1} per tile
        #pragma unroll
        for (int T = 0; T < NT; T++) {
            const int r0w = rowbase + T*8 + 2*m, r1w = r0w + 1;
            sris[r0w*RIS_STRIDE + g    ] = (acc[T][0].x + acc[T][1].x) + acc[T][2].x;
            sris[r1w*RIS_STRIDE + g    ] = (acc[T][0].y + acc[T][1].y) + acc[T][2].y;
            sris[r0w*RIS_STRIDE + g + 8] = (acc[T][0].z + acc[T][1].z) + acc[T][2].z;
            sris[r1w*RIS_STRIDE + g + 8] = (acc[T][0].w + acc[T][1].w) + acc[T][2].w;
        }
        __syncwarp();
    }

    // Output reads rows written by other warps -> CTA-wide barrier (R11 lesson).
    __syncthreads();

    // ---- output projection: out[c] = sum_a Uo[a,c] * ris[a] ----
    if (tid < ROWS_PER_CTA) {
        const long long orow = cta_row0 + tid;
        if (orow < NROWS) {
            const float4* rp = (const float4*)&sris[tid * RIS_STRIDE];
            float4 q0 = rp[0], q1 = rp[1], q2 = rp[2], q3 = rp[3];
            float rv[16] = { q0.x,q0.y,q0.z,q0.w, q1.x,q1.y,q1.z,q1.w,
                             q2.x,q2.y,q2.z,q2.w, q3.x,q3.y,q3.z,q3.w };
            float o[16];
            #pragma unroll
            for (int c = 0; c < 16; c++) o[c] = 0.f;
            #pragma unroll
            for (int a = 0; a < 16; a++) {
                float ra = rv[a];
                #pragma unroll
                for (int c = 0; c < 16; c++) o[c] = fmaf(sUo[a*16 + c], ra, o[c]);
            }
            float4* op = (float4*)(out + (size_t)orow * 16);
            #pragma unroll
            for (int q = 0; q < 4; q++)
                op[q] = make_float4(o[4*q], o[4*q+1], o[4*q+2], o[4*q+3]);
        }
    }
}

extern "C" void kernel_launch(void* const* d_in, const int* in_sizes, int n_in,
                              void* d_out, int out_size)
{
    const float* ns = (const float*)d_in[0];
    const float* U0 = (const float*)d_in[1];
    const float* Ur = (const float*)d_in[2];
    const float* Uo = (const float*)d_in[3];
    float* out = (float*)d_out;

    // stage 1: build the U fragment table (9*16*32 = 4608 work items)
    build_ufrag_kernel<<<9, 512>>>(Ur);

    // stage 2: main TT aggregation
    int grid = (NROWS + ROWS_PER_CTA - 1) / ROWS_PER_CTA;
    tt_mma_kernel<<<grid, TPB, SMEM_BYTES>>>(ns, U0, Uo, out);
}